// round 6
// baseline (speedup 1.0000x reference)
#include <cuda_runtime.h>

// Problem constants (fixed by setup_inputs)
#define Bq 8
#define Cc 64
#define Hh 200
#define Ww 320
#define Nn 48
#define WD 80                       // W / STRIDE
static constexpr float FSTRIDE = 4.0f;   // pad_w / W = 1280 / 320
static constexpr float NEGV = -100000000.0f;

#define TILE 64                     // pixels per tile
#define NC4 (Cc / 4)                // 16 channel quads

// Scratch (no allocation allowed):
// transposed fused weights: W2t[b][c4][n][cc]  (float4 per (b,c4,n))
__device__ float g_W2t[Bq * NC4 * Nn * 4];
__device__ float g_b2[Bq * Nn];

// ---- packed f32x2 helpers (FFMA2 path, PTX-only) ---------------------------
__device__ __forceinline__ unsigned long long pack_dup(float w) {
    unsigned long long r;
    asm("mov.b64 %0, {%1, %1};" : "=l"(r) : "f"(w));
    return r;
}
__device__ __forceinline__ unsigned long long pack2(float a, float b) {
    unsigned long long r;
    asm("mov.b64 %0, {%1, %2};" : "=l"(r) : "f"(a), "f"(b));
    return r;
}
__device__ __forceinline__ void fma2(unsigned long long& acc,
                                     unsigned long long a,
                                     unsigned long long b) {
    asm("fma.rn.f32x2 %0, %1, %2, %0;" : "+l"(acc) : "l"(a), "l"(b));
}
__device__ __forceinline__ float2 unpack2(unsigned long long v) {
    float2 r;
    asm("mov.b64 {%0, %1}, %2;" : "=f"(r.x), "=f"(r.y) : "l"(v));
    return r;
}

// ---------------------------------------------------------------------------
// Prep: per (b,n):
//   kfm[c] = mean_w kernel_feats[b,c,idx,w]
//   vk[o]  = bk[o] + Wk[o,:]·kfm ;  wgt=vk[0:64], bias=vk[64]
//   W2[c]  = wgt·Wf[:,c] ;  b2 = wgt·bf + bias
// Writes W2 transposed into g_W2t[b][c/4][n][c%4].
// ---------------------------------------------------------------------------
__global__ void prep_kernel(const float* __restrict__ kf,
                            const float* __restrict__ Wk,
                            const float* __restrict__ bk,
                            const float* __restrict__ Wf,
                            const float* __restrict__ bf,
                            const float* __restrict__ db,
                            float* __restrict__ centers_out) {
    const int bn  = blockIdx.x;
    const int b   = bn / Nn;
    const int n   = bn % Nn;
    const int tid = threadIdx.x;

    __shared__ float kfm[Cc];
    __shared__ float sW[Cc];
    __shared__ float sBias;

    const float y1 = db[bn * 4 + 1];
    const float y2 = db[bn * 4 + 3];
    const float yc = (y1 + y2) / (2.0f * FSTRIDE);
    const int  idx = (int)yc;
    if (tid == 0) centers_out[bn] = yc * FSTRIDE;

    {   // 2 threads per channel, 10 float4 each, combine via shfl
        const int c    = tid >> 1;
        const int half = tid & 1;
        const float4* p4 = (const float4*)(kf +
            (((size_t)b * Cc + c) * Hh + idx) * WD) + half * 10;
        float s = 0.0f;
        #pragma unroll
        for (int w = 0; w < 10; w++) {
            float4 v = p4[w];
            s += v.x + v.y + v.z + v.w;
        }
        s += __shfl_xor_sync(0xFFFFFFFFu, s, 1);
        if (half == 0) kfm[c] = s * (1.0f / (float)WD);
    }
    __syncthreads();

    if (tid <= Cc) {  // 65 rows of Wk
        float acc = bk[tid];
        const float4* wrow = (const float4*)(Wk + tid * Cc);
        #pragma unroll
        for (int c = 0; c < Cc / 4; c++) {
            float4 v = wrow[c];
            acc += v.x * kfm[c * 4 + 0] + v.y * kfm[c * 4 + 1]
                 + v.z * kfm[c * 4 + 2] + v.w * kfm[c * 4 + 3];
        }
        if (tid < Cc) sW[tid] = acc; else sBias = acc;
    }
    __syncthreads();

    if (tid < Cc) {
        const int c = tid;
        float acc = 0.0f;
        #pragma unroll 16
        for (int o = 0; o < Cc; o++) acc += sW[o] * Wf[o * Cc + c];
        // transposed store: [b][c4][n][cc]
        g_W2t[(((size_t)b * NC4 + (c >> 2)) * Nn + n) * 4 + (c & 3)] = acc;
    } else if (tid == Cc) {
        float acc = sBias;
        for (int o = 0; o < Cc; o++) acc += sW[o] * bf[o];
        g_b2[bn] = acc;
    }
}

// ---------------------------------------------------------------------------
// Main: logits[b,n,h,w] = W2[b,n,:]·feats[b,:,h,w] + b2[b,n], masked.
// Block = (b, h, 64-px tile), 256 threads = 8 warps, NO smem, NO syncthreads.
// Warp grid: 2 px-halves (32 px) x 4 n-quarters (12 n).
// Thread: pg = lane&7 (4 px), ng = lane>>3; n = wn*12 + ng + 4j (j<3).
// Pixel LDG.128: lanes 0-7 cover one 128B line (upper lanes broadcast-dedup);
// L1-hit for the second px-half... no wait, the *other n-quarter warps* hit L1.
// Weight LDG.128: 4 consecutive n rows -> 64B contiguous, L1-hot (g_W2t is
// 98KB total, L2-resident; each block re-reads 12KB/batch through L1).
// Pixel loads register-double-buffered across the c4 loop.
// ---------------------------------------------------------------------------
__global__ __launch_bounds__(256, 3)
void main_kernel(const float* __restrict__ feats,
                 const int* __restrict__ imshape,
                 float* __restrict__ logits) {
    const int b   = blockIdx.z;
    const int h   = blockIdx.y;
    const int w0  = blockIdx.x * TILE;
    const int tid = threadIdx.x;

    const int hlim = (int)((float)imshape[b * 2 + 1] / FSTRIDE);
    const int wlim = (int)((float)imshape[b * 2 + 0] / FSTRIDE);

    float* outbase = logits + ((size_t)b * Nn * Hh + h) * Ww + w0;

    if (h >= hlim || w0 >= wlim) {
        // fully masked tile: 48 n x 64 px = 768 float4, 3 per thread
        const float4 fill = make_float4(NEGV, NEGV, NEGV, NEGV);
        #pragma unroll
        for (int k = 0; k < 3; k++) {
            int i = tid + k * 256;
            int n = i >> 4, q = i & 15;
            *(float4*)(outbase + (size_t)n * Hh * Ww + q * 4) = fill;
        }
        return;
    }

    const int lane = tid & 31;
    const int wrp  = tid >> 5;     // 0..7
    const int wpx  = wrp & 1;      // px half
    const int wn   = wrp >> 1;     // n quarter (12 n)
    const int pg   = lane & 7;
    const int ng   = lane >> 3;
    const int pbase = wpx * 8 + pg;        // float4 index in 16-wide row
    const int px0   = pbase * 4;
    const int nbase = wn * 12 + ng;        // n = nbase + 4*j, j<3

    // accumulators: 3 n-rows x 2 pixel-pairs, init with bias
    unsigned long long acc[3][2];
    #pragma unroll
    for (int j = 0; j < 3; j++) {
        float b2v = __ldg(&g_b2[b * Nn + nbase + 4 * j]);
        acc[j][0] = pack_dup(b2v);
        acc[j][1] = acc[j][0];
    }

    const float4* fsrc = (const float4*)(feats +
        (((size_t)b * Cc) * Hh + h) * Ww + w0);
    const size_t cq = ((size_t)Hh * Ww) >> 2;        // float4 stride per channel
    const float4* wsrc = ((const float4*)g_W2t) + (size_t)b * NC4 * Nn + nbase;

    // prefetch c4 = 0 pixels
    float4 fcur[4];
    #pragma unroll
    for (int cc = 0; cc < 4; cc++)
        fcur[cc] = __ldg(fsrc + cc * cq + pbase);

    #pragma unroll 1
    for (int c4 = 0; c4 < NC4 - 1; c4++) {
        float4 fnext[4];
        #pragma unroll
        for (int cc = 0; cc < 4; cc++)
            fnext[cc] = __ldg(fsrc + ((c4 + 1) * 4 + cc) * cq + pbase);

        float4 w4[3];
        #pragma unroll
        for (int j = 0; j < 3; j++)
            w4[j] = __ldg(wsrc + c4 * Nn + 4 * j);

        unsigned long long fp[4][2];
        #pragma unroll
        for (int cc = 0; cc < 4; cc++) {
            fp[cc][0] = pack2(fcur[cc].x, fcur[cc].y);
            fp[cc][1] = pack2(fcur[cc].z, fcur[cc].w);
        }
        #pragma unroll
        for (int j = 0; j < 3; j++) {
            unsigned long long wp;
            wp = pack_dup(w4[j].x); fma2(acc[j][0], fp[0][0], wp); fma2(acc[j][1], fp[0][1], wp);
            wp = pack_dup(w4[j].y); fma2(acc[j][0], fp[1][0], wp); fma2(acc[j][1], fp[1][1], wp);
            wp = pack_dup(w4[j].z); fma2(acc[j][0], fp[2][0], wp); fma2(acc[j][1], fp[2][1], wp);
            wp = pack_dup(w4[j].w); fma2(acc[j][0], fp[3][0], wp); fma2(acc[j][1], fp[3][1], wp);
        }
        #pragma unroll
        for (int cc = 0; cc < 4; cc++) fcur[cc] = fnext[cc];
    }
    {   // final c4 iteration (no prefetch)
        const int c4 = NC4 - 1;
        float4 w4[3];
        #pragma unroll
        for (int j = 0; j < 3; j++)
            w4[j] = __ldg(wsrc + c4 * Nn + 4 * j);

        unsigned long long fp[4][2];
        #pragma unroll
        for (int cc = 0; cc < 4; cc++) {
            fp[cc][0] = pack2(fcur[cc].x, fcur[cc].y);
            fp[cc][1] = pack2(fcur[cc].z, fcur[cc].w);
        }
        #pragma unroll
        for (int j = 0; j < 3; j++) {
            unsigned long long wp;
            wp = pack_dup(w4[j].x); fma2(acc[j][0], fp[0][0], wp); fma2(acc[j][1], fp[0][1], wp);
            wp = pack_dup(w4[j].y); fma2(acc[j][0], fp[1][0], wp); fma2(acc[j][1], fp[1][1], wp);
            wp = pack_dup(w4[j].z); fma2(acc[j][0], fp[2][0], wp); fma2(acc[j][1], fp[2][1], wp);
            wp = pack_dup(w4[j].w); fma2(acc[j][0], fp[3][0], wp); fma2(acc[j][1], fp[3][1], wp);
        }
    }

    const int nvalid = wlim - w0;   // > 0 on this path
    #pragma unroll
    for (int j = 0; j < 3; j++) {
        const int n = nbase + 4 * j;
        float2 lo = unpack2(acc[j][0]);
        float2 hi = unpack2(acc[j][1]);
        float4 v;
        v.x = (px0 + 0 < nvalid) ? lo.x : NEGV;
        v.y = (px0 + 1 < nvalid) ? lo.y : NEGV;
        v.z = (px0 + 2 < nvalid) ? hi.x : NEGV;
        v.w = (px0 + 3 < nvalid) ? hi.y : NEGV;
        *(float4*)(outbase + (size_t)n * Hh * Ww + px0) = v;
    }
}

extern "C" void kernel_launch(void* const* d_in, const int* in_sizes, int n_in,
                              void* d_out, int out_size) {
    const float* feats   = (const float*)d_in[0];
    const float* kf      = (const float*)d_in[1];
    const float* Wk      = (const float*)d_in[2];
    const float* bk      = (const float*)d_in[3];
    const float* Wf      = (const float*)d_in[4];
    const float* bf      = (const float*)d_in[5];
    const float* db      = (const float*)d_in[6];
    const int*   imshape = (const int*)d_in[7];

    float* logits  = (float*)d_out;
    float* centers = logits + (size_t)Bq * Nn * Hh * Ww;

    prep_kernel<<<Bq * Nn, 128>>>(kf, Wk, bk, Wf, bf, db, centers);
    main_kernel<<<dim3(Ww / TILE, Hh, Bq), 256>>>(feats, imshape, logits);
}

// round 7
// speedup vs baseline: 1.2292x; 1.2292x over previous
#include <cuda_runtime.h>

// Problem constants (fixed by setup_inputs)
#define Bq 8
#define Cc 64
#define Hh 200
#define Ww 320
#define Nn 48
#define WD 80                       // W / STRIDE
static constexpr float FSTRIDE = 4.0f;   // pad_w / W = 1280 / 320
static constexpr float NEGV = -100000000.0f;

#define TILE 64                     // pixels per tile
#define NC4 (Cc / 4)                // 16 channel quads
#define GROUP 8                     // h rows per block
#define NTHREADS 256

// Scratch (no allocation allowed):
// transposed fused weights: W2t[b][c4][n][cc]  (one float4 per (b,c4,n))
__device__ float g_W2t[Bq * NC4 * Nn * 4];
__device__ float g_b2[Bq * Nn];

// ---- packed f32x2 helpers (FFMA2 path, PTX-only) ---------------------------
__device__ __forceinline__ unsigned long long pack_dup(float w) {
    unsigned long long r;
    asm("mov.b64 %0, {%1, %1};" : "=l"(r) : "f"(w));
    return r;
}
__device__ __forceinline__ unsigned long long pack2(float a, float b) {
    unsigned long long r;
    asm("mov.b64 %0, {%1, %2};" : "=l"(r) : "f"(a), "f"(b));
    return r;
}
__device__ __forceinline__ void fma2(unsigned long long& acc,
                                     unsigned long long a,
                                     unsigned long long b) {
    asm("fma.rn.f32x2 %0, %1, %2, %0;" : "+l"(acc) : "l"(a), "l"(b));
}
__device__ __forceinline__ float2 unpack2(unsigned long long v) {
    float2 r;
    asm("mov.b64 {%0, %1}, %2;" : "=f"(r.x), "=f"(r.y) : "l"(v));
    return r;
}
// ---- cp.async helpers -------------------------------------------------------
__device__ __forceinline__ void cp_async16(void* smem_dst, const void* gmem_src) {
    unsigned s = (unsigned)__cvta_generic_to_shared(smem_dst);
    asm volatile("cp.async.cg.shared.global [%0], [%1], 16;\n" :: "r"(s), "l"(gmem_src));
}
__device__ __forceinline__ void cp_commit() {
    asm volatile("cp.async.commit_group;\n");
}
__device__ __forceinline__ void cp_wait1() {
    asm volatile("cp.async.wait_group 1;\n");
}

// ---------------------------------------------------------------------------
// Prep: per (b,n):
//   kfm[c] = mean_w kernel_feats[b,c,idx,w]
//   vk[o]  = bk[o] + Wk[o,:]·kfm ;  wgt=vk[0:64], bias=vk[64]
//   W2[c]  = wgt·Wf[:,c] ;  b2 = wgt·bf + bias
// Writes W2 transposed into g_W2t[b][c/4][n][c%4].
// ---------------------------------------------------------------------------
__global__ void prep_kernel(const float* __restrict__ kf,
                            const float* __restrict__ Wk,
                            const float* __restrict__ bk,
                            const float* __restrict__ Wf,
                            const float* __restrict__ bf,
                            const float* __restrict__ db,
                            float* __restrict__ centers_out) {
    const int bn  = blockIdx.x;
    const int b   = bn / Nn;
    const int n   = bn % Nn;
    const int tid = threadIdx.x;

    __shared__ float kfm[Cc];
    __shared__ float sW[Cc];
    __shared__ float sBias;

    const float y1 = db[bn * 4 + 1];
    const float y2 = db[bn * 4 + 3];
    const float yc = (y1 + y2) / (2.0f * FSTRIDE);
    const int  idx = (int)yc;
    if (tid == 0) centers_out[bn] = yc * FSTRIDE;

    {   // 2 threads per channel, 10 float4 each, combine via shfl
        const int c    = tid >> 1;
        const int half = tid & 1;
        const float4* p4 = (const float4*)(kf +
            (((size_t)b * Cc + c) * Hh + idx) * WD) + half * 10;
        float s = 0.0f;
        #pragma unroll
        for (int w = 0; w < 10; w++) {
            float4 v = p4[w];
            s += v.x + v.y + v.z + v.w;
        }
        s += __shfl_xor_sync(0xFFFFFFFFu, s, 1);
        if (half == 0) kfm[c] = s * (1.0f / (float)WD);
    }
    __syncthreads();

    if (tid <= Cc) {  // 65 rows of Wk
        float acc = bk[tid];
        const float4* wrow = (const float4*)(Wk + tid * Cc);
        #pragma unroll
        for (int c = 0; c < Cc / 4; c++) {
            float4 v = wrow[c];
            acc += v.x * kfm[c * 4 + 0] + v.y * kfm[c * 4 + 1]
                 + v.z * kfm[c * 4 + 2] + v.w * kfm[c * 4 + 3];
        }
        if (tid < Cc) sW[tid] = acc; else sBias = acc;
    }
    __syncthreads();

    if (tid < Cc) {
        const int c = tid;
        float acc = 0.0f;
        #pragma unroll 16
        for (int o = 0; o < Cc; o++) acc += sW[o] * Wf[o * Cc + c];
        // transposed store: [b][c4][n][cc]
        g_W2t[(((size_t)b * NC4 + (c >> 2)) * Nn + n) * 4 + (c & 3)] = acc;
    } else if (tid == Cc) {
        float acc = sBias;
        for (int o = 0; o < Cc; o++) acc += sW[o] * bf[o];
        g_b2[bn] = acc;
    }
}

// ---------------------------------------------------------------------------
// Main: logits[b,n,h,w] = W2[b,n,:]·feats[b,:,h,w] + b2[b,n], masked.
// Block = (b, 8-row h group, 64-px tile), 256 threads = 8 warps.
// Warp grid: 2 px-halves (32 px) x 4 n-quarters (12 n); thread: 3 n x 4 px.
// Pixels: cp.async double-buffered rows in smem; LDS.128 1-phase broadcast.
// Weights: LDG.128 from transposed g_W2t (L2-resident, L1-hot across the
//          block's 8 rows); 4 consecutive n per 8-lane group = 64B coalesced.
// ---------------------------------------------------------------------------
__global__ __launch_bounds__(NTHREADS, 4)
void main_kernel(const float* __restrict__ feats,
                 const int* __restrict__ imshape,
                 float* __restrict__ logits) {
    const int b   = blockIdx.z;
    const int h0  = blockIdx.y * GROUP;
    const int w0  = blockIdx.x * TILE;
    const int tid = threadIdx.x;

    const int hlim = (int)((float)imshape[b * 2 + 1] / FSTRIDE);
    const int wlim = (int)((float)imshape[b * 2 + 0] / FSTRIDE);

    const float4 fillv = make_float4(NEGV, NEGV, NEGV, NEGV);
    int nrows = (w0 < wlim) ? min(GROUP, max(0, hlim - h0)) : 0;

    // fill all masked rows of the group (independent stores, no sync needed)
    for (int g = nrows; g < GROUP; g++) {
        float* ob = logits + ((size_t)b * Nn * Hh + (h0 + g)) * Ww + w0;
        #pragma unroll
        for (int k = 0; k < 3; k++) {
            int i = tid + k * NTHREADS;
            int n = i >> 4, q = i & 15;
            *(float4*)(ob + (size_t)n * Hh * Ww + q * 4) = fillv;
        }
    }
    if (nrows == 0) return;

    __shared__ float Fs[2][Cc * TILE];        // 2 x 16 KB

    const float* rowsrc = feats + ((size_t)b * Cc * Hh + h0) * Ww + w0;
    const size_t chanstride = (size_t)Hh * Ww;

    // prefetch row 0 into buffer 0: 1024 float4, 4 per thread
    {
        #pragma unroll
        for (int k = 0; k < 4; k++) {
            int i = tid + k * NTHREADS;
            int c = i >> 4, q = i & 15;
            cp_async16(&Fs[0][c * TILE + q * 4],
                       rowsrc + (size_t)c * chanstride + q * 4);
        }
    }
    cp_commit();

    const int lane = tid & 31;
    const int wrp  = tid >> 5;     // 0..7
    const int wpx  = wrp & 1;      // px half (32 px)
    const int wn   = wrp >> 1;     // n quarter (12 n)
    const int pg   = lane & 7;
    const int ng   = lane >> 3;
    const int pbase = wpx * 8 + pg;        // float4 index in 16-wide row
    const int px0   = pbase * 4;
    const int nbase = wn * 12 + ng;        // n = nbase + 4*j, j<3

    unsigned long long b2p[3];
    #pragma unroll
    for (int j = 0; j < 3; j++)
        b2p[j] = pack_dup(__ldg(&g_b2[b * Nn + nbase + 4 * j]));

    const float4* wsrc = ((const float4*)g_W2t) + (size_t)b * NC4 * Nn + nbase;
    const int nvalid = wlim - w0;   // > 0 here

    for (int g = 0; g < nrows; g++) {
        // prefetch next row into the other buffer
        if (g + 1 < nrows) {
            const float* src = rowsrc + (size_t)(g + 1) * Ww;
            float* dst = Fs[(g + 1) & 1];
            #pragma unroll
            for (int k = 0; k < 4; k++) {
                int i = tid + k * NTHREADS;
                int c = i >> 4, q = i & 15;
                cp_async16(&dst[c * TILE + q * 4],
                           src + (size_t)c * chanstride + q * 4);
            }
        }
        cp_commit();
        cp_wait1();            // row g's data has arrived
        __syncthreads();

        const float4* Fs4 = (const float4*)Fs[g & 1];

        unsigned long long acc[3][2];
        #pragma unroll
        for (int j = 0; j < 3; j++) { acc[j][0] = b2p[j]; acc[j][1] = b2p[j]; }

        #pragma unroll 2
        for (int c4 = 0; c4 < NC4; c4++) {
            // weights for this c4 (L1-hot across rows)
            float4 w4[3];
            #pragma unroll
            for (int j = 0; j < 3; j++)
                w4[j] = __ldg(wsrc + c4 * Nn + 4 * j);

            unsigned long long fp[4][2];
            #pragma unroll
            for (int cc = 0; cc < 4; cc++) {
                float4 fv = Fs4[(c4 * 4 + cc) * (TILE / 4) + pbase];
                fp[cc][0] = pack2(fv.x, fv.y);
                fp[cc][1] = pack2(fv.z, fv.w);
            }
            #pragma unroll
            for (int j = 0; j < 3; j++) {
                unsigned long long wp;
                wp = pack_dup(w4[j].x); fma2(acc[j][0], fp[0][0], wp); fma2(acc[j][1], fp[0][1], wp);
                wp = pack_dup(w4[j].y); fma2(acc[j][0], fp[1][0], wp); fma2(acc[j][1], fp[1][1], wp);
                wp = pack_dup(w4[j].z); fma2(acc[j][0], fp[2][0], wp); fma2(acc[j][1], fp[2][1], wp);
                wp = pack_dup(w4[j].w); fma2(acc[j][0], fp[3][0], wp); fma2(acc[j][1], fp[3][1], wp);
            }
        }

        float* ob = logits + ((size_t)b * Nn * Hh + (h0 + g)) * Ww + w0;
        #pragma unroll
        for (int j = 0; j < 3; j++) {
            const int n = nbase + 4 * j;
            float2 lo = unpack2(acc[j][0]);
            float2 hi = unpack2(acc[j][1]);
            float4 v;
            v.x = (px0 + 0 < nvalid) ? lo.x : NEGV;
            v.y = (px0 + 1 < nvalid) ? lo.y : NEGV;
            v.z = (px0 + 2 < nvalid) ? hi.x : NEGV;
            v.w = (px0 + 3 < nvalid) ? hi.y : NEGV;
            *(float4*)(ob + (size_t)n * Hh * Ww + px0) = v;
        }
        __syncthreads();   // all warps done with Fs[g&1] before refill
    }
}

extern "C" void kernel_launch(void* const* d_in, const int* in_sizes, int n_in,
                              void* d_out, int out_size) {
    const float* feats   = (const float*)d_in[0];
    const float* kf      = (const float*)d_in[1];
    const float* Wk      = (const float*)d_in[2];
    const float* bk      = (const float*)d_in[3];
    const float* Wf      = (const float*)d_in[4];
    const float* bf      = (const float*)d_in[5];
    const float* db      = (const float*)d_in[6];
    const int*   imshape = (const int*)d_in[7];

    float* logits  = (float*)d_out;
    float* centers = logits + (size_t)Bq * Nn * Hh * Ww;

    prep_kernel<<<Bq * Nn, 128>>>(kf, Wk, bk, Wf, bf, db, centers);
    main_kernel<<<dim3(Ww / TILE, Hh / GROUP, Bq), NTHREADS>>>(feats, imshape, logits);
}

// round 8
// speedup vs baseline: 2.5867x; 2.1044x over previous
#include <cuda_runtime.h>
#include <cstdint>

// Problem constants (fixed by setup_inputs)
#define Bq 8
#define Cc 64
#define Hh 200
#define Ww 320
#define Nn 48
#define WD 80                       // W / STRIDE
static constexpr float FSTRIDE = 4.0f;   // pad_w / W = 1280 / 320
static constexpr float NEGV = -100000000.0f;

#define TILE 64                     // pixels per tile
#define NKK 8                       // k-steps: 64 ch / 8
#define NMM 3                       // m-tiles: 48 dets / 16

// Scratch (no allocation allowed):
// weights pre-packed in mma.m16n8k8 A-fragment layout, tf32-rounded:
//   g_Wfrag[b][kk][mm][lane][reg]
__device__ float g_Wfrag[Bq * NKK * NMM * 32 * 4];
__device__ float g_b2[Bq * Nn];

// ---- tf32 mma.sync m16n8k8 --------------------------------------------------
__device__ __forceinline__ void mma_tf32(float* d, const uint4& a,
                                         uint32_t b0, uint32_t b1) {
    asm volatile(
        "mma.sync.aligned.m16n8k8.row.col.f32.tf32.tf32.f32 "
        "{%0,%1,%2,%3}, {%4,%5,%6,%7}, {%8,%9}, {%0,%1,%2,%3};"
        : "+f"(d[0]), "+f"(d[1]), "+f"(d[2]), "+f"(d[3])
        : "r"(a.x), "r"(a.y), "r"(a.z), "r"(a.w), "r"(b0), "r"(b1));
}

// ---------------------------------------------------------------------------
// Prep: per (b,n):
//   kfm[c] = mean_w kernel_feats[b,c,idx,w]
//   vk[o]  = bk[o] + Wk[o,:]·kfm ;  wgt=vk[0:64], bias=vk[64]
//   W2[c]  = wgt·Wf[:,c] ;  b2 = wgt·bf + bias
// W2 is rounded to tf32 and scattered into mma A-fragment layout g_Wfrag.
// Fragment map (m16n8k8 row-major A): for element (n_local, c_local) of a
// 16x8 tile: lane = (n&7)*4 + (c&3), reg = ((n>>3)&1) + 2*((c>>2)&1).
// ---------------------------------------------------------------------------
__global__ void prep_kernel(const float* __restrict__ kf,
                            const float* __restrict__ Wk,
                            const float* __restrict__ bk,
                            const float* __restrict__ Wf,
                            const float* __restrict__ bf,
                            const float* __restrict__ db,
                            float* __restrict__ centers_out) {
    const int bn  = blockIdx.x;
    const int b   = bn / Nn;
    const int n   = bn % Nn;
    const int tid = threadIdx.x;

    __shared__ float kfm[Cc];
    __shared__ float sW[Cc];
    __shared__ float sBias;

    const float y1 = db[bn * 4 + 1];
    const float y2 = db[bn * 4 + 3];
    const float yc = (y1 + y2) / (2.0f * FSTRIDE);
    const int  idx = (int)yc;
    if (tid == 0) centers_out[bn] = yc * FSTRIDE;

    {   // 2 threads per channel, 10 float4 each, combine via shfl
        const int c    = tid >> 1;
        const int half = tid & 1;
        const float4* p4 = (const float4*)(kf +
            (((size_t)b * Cc + c) * Hh + idx) * WD) + half * 10;
        float s = 0.0f;
        #pragma unroll
        for (int w = 0; w < 10; w++) {
            float4 v = p4[w];
            s += v.x + v.y + v.z + v.w;
        }
        s += __shfl_xor_sync(0xFFFFFFFFu, s, 1);
        if (half == 0) kfm[c] = s * (1.0f / (float)WD);
    }
    __syncthreads();

    if (tid <= Cc) {  // 65 rows of Wk
        float acc = bk[tid];
        const float4* wrow = (const float4*)(Wk + tid * Cc);
        #pragma unroll
        for (int c = 0; c < Cc / 4; c++) {
            float4 v = wrow[c];
            acc += v.x * kfm[c * 4 + 0] + v.y * kfm[c * 4 + 1]
                 + v.z * kfm[c * 4 + 2] + v.w * kfm[c * 4 + 3];
        }
        if (tid < Cc) sW[tid] = acc; else sBias = acc;
    }
    __syncthreads();

    if (tid < Cc) {
        const int c = tid;
        float acc = 0.0f;
        #pragma unroll 16
        for (int o = 0; o < Cc; o++) acc += sW[o] * Wf[o * Cc + c];
        uint32_t t;
        asm("cvt.rna.tf32.f32 %0, %1;" : "=r"(t) : "f"(acc));
        const int kk = c >> 3, tig = c & 3, colhalf = (c >> 2) & 1;
        const int mm = n >> 4, gid = n & 7, rowhalf = (n >> 3) & 1;
        const int lane = gid * 4 + tig;
        g_Wfrag[((((b * NKK + kk) * NMM + mm) * 32 + lane) << 2)
                + rowhalf + 2 * colhalf] = __uint_as_float(t);
    } else if (tid == Cc) {
        float acc = sBias;
        for (int o = 0; o < Cc; o++) acc += sW[o] * bf[o];
        g_b2[bn] = acc;
    }
}

// ---------------------------------------------------------------------------
// Main: logits[b,n,h,w] = W2[b,n,:]·feats[b,:,h,w] + b2[b,n], masked.
// Block = (b, h, 64-px tile), 128 threads = 4 warps, each warp owns 16 px
// and ALL 48 n via tf32 mma.m16n8k8 (3 m-tiles x 2 px-frags x 8 k-steps).
// A-frags: LDS.128 from pre-packed Wfs. B-frags: LDS.32 from quad-swizzled
// Fs ((q + 2*(c&3))&15) -> bank-conflict-free. D stays in registers.
// ---------------------------------------------------------------------------
__global__ __launch_bounds__(128, 6)
void main_kernel(const float* __restrict__ feats,
                 const int* __restrict__ imshape,
                 float* __restrict__ logits) {
    const int b   = blockIdx.z;
    const int h   = blockIdx.y;
    const int w0  = blockIdx.x * TILE;
    const int tid = threadIdx.x;

    const int hlim = (int)((float)imshape[b * 2 + 1] / FSTRIDE);
    const int wlim = (int)((float)imshape[b * 2 + 0] / FSTRIDE);

    float* outbase = logits + ((size_t)b * Nn * Hh + h) * Ww + w0;

    if (h >= hlim || w0 >= wlim) {
        // fully masked tile: 48 n x 64 px = 768 float4, 6 per thread
        const float4 fill = make_float4(NEGV, NEGV, NEGV, NEGV);
        #pragma unroll
        for (int k = 0; k < 6; k++) {
            int i = tid + k * 128;
            int n = i >> 4, q = i & 15;
            *(float4*)(outbase + (size_t)n * Hh * Ww + q * 4) = fill;
        }
        return;
    }

    __shared__ float Wfs[NKK * NMM * 32 * 4];   // 12 KB, fragment layout
    __shared__ float Fs[Cc * TILE];             // 16 KB, quad-swizzled

    // stage weight fragments: 768 float4, contiguous copy
    {
        const float4* wg = (const float4*)(g_Wfrag + (size_t)b * NKK * NMM * 128);
        float4* ws = (float4*)Wfs;
        #pragma unroll
        for (int k = 0; k < 6; k++)
            ws[tid + k * 128] = wg[tid + k * 128];
    }
    // stage feats tile with quad swizzle: store quad q of channel c at
    // quad (q + 2*(c&3)) & 15  ->  word px' = (px + 8*(c&3)) & 63
    {
        const float4* src = (const float4*)(feats +
            (((size_t)b * Cc) * Hh + h) * Ww + w0);
        const size_t cq = ((size_t)Hh * Ww) >> 2;
        #pragma unroll
        for (int k = 0; k < 8; k++) {
            int i = tid + k * 128;
            int c = i >> 4, q = i & 15;
            float4 v = src[(size_t)c * cq + q];
            int qs = (q + 2 * (c & 3)) & 15;
            ((float4*)Fs)[c * 16 + qs] = v;
        }
    }
    __syncthreads();

    const int lane = tid & 31;
    const int wrp  = tid >> 5;     // 0..3, warp owns px [wrp*16, wrp*16+16)
    const int gid  = lane >> 2;    // 0..7
    const int tig  = lane & 3;     // 0..3
    const int pxbase = wrp * 16;

    // accumulators: 3 m-tiles x 2 px-frags x 4 regs, init with bias
    float acc[NMM][2][4];
    #pragma unroll
    for (int m = 0; m < NMM; m++) {
        float b0 = __ldg(&g_b2[b * Nn + m * 16 + gid]);
        float b1 = __ldg(&g_b2[b * Nn + m * 16 + gid + 8]);
        #pragma unroll
        for (int f = 0; f < 2; f++) {
            acc[m][f][0] = b0; acc[m][f][1] = b0;
            acc[m][f][2] = b1; acc[m][f][3] = b1;
        }
    }

    #pragma unroll
    for (int kk = 0; kk < NKK; kk++) {
        uint4 a[NMM];
        #pragma unroll
        for (int m = 0; m < NMM; m++)
            a[m] = *(const uint4*)&Wfs[(((kk * NMM) + m) * 32 + lane) << 2];

        uint32_t bb[2][2];
        #pragma unroll
        for (int f = 0; f < 2; f++) {
            int px  = pxbase + f * 8 + gid;
            int pxs = (px + 8 * tig) & 63;
            bb[f][0] = __float_as_uint(Fs[(kk * 8 + tig) * 64 + pxs]);
            bb[f][1] = __float_as_uint(Fs[(kk * 8 + tig + 4) * 64 + pxs]);
        }
        #pragma unroll
        for (int m = 0; m < NMM; m++)
            #pragma unroll
            for (int f = 0; f < 2; f++)
                mma_tf32(acc[m][f], a[m], bb[f][0], bb[f][1]);
    }

    // epilogue: mask + store, D-frag (row gid/gid+8, cols 2tig, 2tig+1)
    const int nvalid = wlim - w0;   // > 0 on this path
    const size_t HW = (size_t)Hh * Ww;
    #pragma unroll
    for (int m = 0; m < NMM; m++) {
        #pragma unroll
        for (int f = 0; f < 2; f++) {
            const int px = pxbase + f * 8 + 2 * tig;
            const bool v0 = px < nvalid, v1 = px + 1 < nvalid;
            const int n0 = m * 16 + gid, n1 = n0 + 8;
            float2 lo, hi;
            lo.x = v0 ? acc[m][f][0] : NEGV;
            lo.y = v1 ? acc[m][f][1] : NEGV;
            hi.x = v0 ? acc[m][f][2] : NEGV;
            hi.y = v1 ? acc[m][f][3] : NEGV;
            *(float2*)(outbase + n0 * HW + px) = lo;
            *(float2*)(outbase + n1 * HW + px) = hi;
        }
    }
}

extern "C" void kernel_launch(void* const* d_in, const int* in_sizes, int n_in,
                              void* d_out, int out_size) {
    const float* feats   = (const float*)d_in[0];
    const float* kf      = (const float*)d_in[1];
    const float* Wk      = (const float*)d_in[2];
    const float* bk      = (const float*)d_in[3];
    const float* Wf      = (const float*)d_in[4];
    const float* bf      = (const float*)d_in[5];
    const float* db      = (const float*)d_in[6];
    const int*   imshape = (const int*)d_in[7];

    float* logits  = (float*)d_out;
    float* centers = logits + (size_t)Bq * Nn * Hh * Ww;

    prep_kernel<<<Bq * Nn, 128>>>(kf, Wk, bk, Wf, bf, db, centers);
    main_kernel<<<dim3(Ww / TILE, Hh, Bq), 128>>>(feats, imshape, logits);
}